// round 4
// baseline (speedup 1.0000x reference)
#include <cuda_runtime.h>
#include <cstdint>

// PointerNet_30949534335591
//
// Mathematical reduction (verified R2: passed, rel_err = 0.0, 5.0 us):
// ptr_W has shape (1, H), so logits = h @ ptr_W.T + ptr_b is [B, 1];
// argmax over axis=1 of a single-column tensor is identically 0 for
// every row and every of the S decoder steps ("always 0, faithful to
// source" per the reference). The output ptrs.T is a constant zeros
// tensor of shape [B, S] = [256, 512], independent of all 11 inputs.
// Both LSTM scans are dead code w.r.t. the observable output.
//
// R2 ncu: DRAM 0.0%, L2 1.5%, occ 9.2% — the 512 KB of zero-stores are
// free; all remaining time is launch overhead. Lever: a graph memset
// node (cudaMemsetAsync — async, allocation-free, capture-legal)
// instead of a user kernel launch.
//
// R3 bench was a broker-level container failure (same error as R0/R1,
// where the identical-at-the-time kernel later passed unchanged) — no
// evidence against the memset. Retrying.
//
// Fallback (proven 5.0 us in R2) if a genuine rule-violation appears:
//   __global__ void zero_k(int4* o, int n4) {
//     int i = blockIdx.x * blockDim.x + threadIdx.x;
//     if (i < n4) o[i] = make_int4(0, 0, 0, 0);
//   }
//   zero_k<<<128, 256>>>((int4*)d_out, out_size >> 2);

extern "C" void kernel_launch(void* const* d_in, const int* in_sizes, int n_in,
                              void* d_out, int out_size) {
    (void)d_in; (void)in_sizes; (void)n_in;
    // Output dtype is int32 (pointer indices); all-zero bytes == int 0.
    cudaMemsetAsync(d_out, 0, (size_t)out_size * sizeof(int));
}